// round 16
// baseline (speedup 1.0000x reference)
#include <cuda_runtime.h>
#include <cuda_fp16.h>
#include <cstdint>

#define HH 512
#define WW 1024
#define HWSZ (HH*WW)

// ---------------- device scratch ----------------
__device__ __half g_actH[2][(size_t)HWSZ*128];
__device__ __half g_actL[2][(size_t)HWSZ*128];
__device__ __half g_inH[(size_t)HWSZ*64];
__device__ __half g_inL[(size_t)HWSZ*64];
__device__ float g_part[(size_t)16*HWSZ];      // per-z partials: [z*4+{r,g,b,sum}][HW]
__device__ __half g_wmH[(size_t)23*9*2*104*64];
__device__ __half g_wmL[(size_t)23*9*2*104*64];
__device__ __half g_w0H[(size_t)9*104*64];
__device__ __half g_w0L[(size_t)9*104*64];
__device__ __half g_wlH[(size_t)9*2*448*64];
__device__ __half g_wlL[(size_t)9*2*448*64];
__device__ float g_bias[24*104];
__device__ float g_biasL[448];

// ---------------- helpers ----------------
__device__ __forceinline__ unsigned smem_u32(const void* p){unsigned a;asm("{ .reg .u64 t; cvta.to.shared.u64 t, %1; cvt.u32.u64 %0, t; }":"=r"(a):"l"(p));return a;}
__device__ __forceinline__ void cpa16(unsigned d,const void* s,int sz){asm volatile("cp.async.cg.shared.global [%0], [%1], 16, %2;"::"r"(d),"l"(s),"r"(sz));}
__device__ __forceinline__ void cpa_commit(){asm volatile("cp.async.commit_group;");}
__device__ __forceinline__ void cpa_wait0(){asm volatile("cp.async.wait_group 0;");}
__device__ __forceinline__ unsigned sw128(unsigned o){return o^((o>>3)&0x70);}
__device__ __forceinline__ void ldsm4(uint32_t* r, unsigned a){
    asm volatile("ldmatrix.sync.aligned.m8n8.x4.shared.b16 {%0,%1,%2,%3}, [%4];"
        :"=r"(r[0]),"=r"(r[1]),"=r"(r[2]),"=r"(r[3]):"r"(a));
}
__device__ __forceinline__ void ldsm2(uint32_t* r, unsigned a){
    asm volatile("ldmatrix.sync.aligned.m8n8.x2.shared.b16 {%0,%1}, [%2];"
        :"=r"(r[0]),"=r"(r[1]):"r"(a));
}
__device__ __forceinline__ void mma16816(float* c, const uint32_t* a, const uint32_t* b){
    asm volatile("mma.sync.aligned.m16n8k16.row.col.f32.f16.f16.f32 "
        "{%0,%1,%2,%3}, {%4,%5,%6,%7}, {%8,%9}, {%0,%1,%2,%3};"
        :"+f"(c[0]),"+f"(c[1]),"+f"(c[2]),"+f"(c[3])
        :"r"(a[0]),"r"(a[1]),"r"(a[2]),"r"(a[3]),"r"(b[0]),"r"(b[1]));
}
__device__ __forceinline__ uint32_t pack_h(float v0,float v1,__half& h0,__half& h1){
    h0=__float2half_rn(v0); h1=__float2half_rn(v1);
    return (unsigned)__half_as_ushort(h0)|((unsigned)__half_as_ushort(h1)<<16);
}

#define AHALO 23040u

// Fully-unrolled compute for one (offset, ch-block) stage; NT N-tiles.
// Pass-major mma order for latency hiding.
template<int KCMAX,int NT>
__device__ __forceinline__ void computeStage(
    unsigned sA, unsigned bB, unsigned bLoff, int rdel,
    int brow0, int brow1, unsigned klane, int nbase, int lane,
    float C[7][2][4])
{
    const int br[2]={brow0,brow1};
    #pragma unroll
    for(int kc=0;kc<KCMAX;kc++){
        uint32_t ah[2][4], al[2][4], bh[7][2], bl[7][2];
        #pragma unroll
        for(int mt=0;mt<2;mt++){
            const unsigned rel=(unsigned)((br[mt]+rdel)*128)+(unsigned)(kc*32)+klane;
            ldsm4(ah[mt], sA+sw128(rel));
            ldsm4(al[mt], sA+AHALO+sw128(rel));
        }
        constexpr int NP=NT/2;
        #pragma unroll
        for(int p=0;p<NP;p++){
            const unsigned rb=(unsigned)((nbase+p*16+(lane&7)+((lane&16)?8:0))*128 + kc*32 + ((lane&8)?16:0));
            uint32_t t4[4];
            ldsm4(t4, bB+sw128(rb));
            bh[2*p][0]=t4[0]; bh[2*p][1]=t4[1]; bh[2*p+1][0]=t4[2]; bh[2*p+1][1]=t4[3];
            ldsm4(t4, bB+bLoff+sw128(rb));
            bl[2*p][0]=t4[0]; bl[2*p][1]=t4[1]; bl[2*p+1][0]=t4[2]; bl[2*p+1][1]=t4[3];
        }
        if(NT&1){
            const unsigned rb6=(unsigned)((nbase+(NP*16)+(lane&7))*128 + kc*32 + ((lane&8)?16:0));
            ldsm2(bh[NT-1], bB+sw128(rb6));
            ldsm2(bl[NT-1], bB+bLoff+sw128(rb6));
        }
        #pragma unroll
        for(int t=0;t<NT;t++)
            #pragma unroll
            for(int mt=0;mt<2;mt++) mma16816(C[t][mt], ah[mt], bh[t]);
        #pragma unroll
        for(int t=0;t<NT;t++)
            #pragma unroll
            for(int mt=0;mt<2;mt++) mma16816(C[t][mt], ah[mt], bl[t]);
        #pragma unroll
        for(int t=0;t<NT;t++)
            #pragma unroll
            for(int mt=0;mt<2;mt++) mma16816(C[t][mt], al[mt], bh[t]);
    }
}

// ---------------- prep kernels ----------------
#define NW0 (9*104*64)
#define NWM (23*18*104*64)
#define NWL (9*2*448*64)
#define NBM (24*104)
#define NBL 448
__global__ void prepW_k(const float* __restrict__ w0,const float* __restrict__ wm,
                        const float* __restrict__ wl,const float* __restrict__ b0,
                        const float* __restrict__ bm,const float* __restrict__ bl){
    int idx=blockIdx.x*blockDim.x+threadIdx.x;
    if(idx<NW0){
        const int j=idx&63, n=(idx>>6)%104, off=(idx>>6)/104;
        float v=(n<100&&j<10)?w0[((size_t)n*10+j)*9+off]:0.f;
        __half h=__float2half_rn(v); g_w0H[idx]=h; g_w0L[idx]=__float2half_rn(v-__half2float(h));
        return;
    }
    idx-=NW0;
    if(idx<NWM){
        const int j=idx&63, n=(idx>>6)%104;
        const int rest=(idx>>6)/104, cb=rest%2, rest2=rest/2, off=rest2%9, l=rest2/9;
        const int ic=cb*64+j;
        float v=(n<100&&ic<100)?wm[(((size_t)l*100+n)*100+ic)*9+off]:0.f;
        __half h=__float2half_rn(v); g_wmH[idx]=h; g_wmL[idx]=__float2half_rn(v-__half2float(h));
        return;
    }
    idx-=NWM;
    if(idx<NWL){
        const int j=idx&63, n=(idx>>6)%448;
        const int rest=(idx>>6)/448, cb=rest%2, off=rest/2;
        const int ic=cb*64+j;
        float v=(n<441&&ic<100)?wl[((size_t)n*100+ic)*9+off]:0.f;
        __half h=__float2half_rn(v); g_wlH[idx]=h; g_wlL[idx]=__float2half_rn(v-__half2float(h));
        return;
    }
    idx-=NWL;
    if(idx<NBM){
        const int n=idx%104,l=idx/104; g_bias[idx]=(n<100)?(l==0?b0[n]:bm[(l-1)*100+n]):0.f;
        return;
    }
    idx-=NBM;
    if(idx<NBL) g_biasL[idx]=(idx<441)?bl[idx]:0.f;
}
__global__ void prepI_k(const float* __restrict__ in){
    const int pix=blockIdx.x*blockDim.x+threadIdx.x; if(pix>=HWSZ) return;
    __half* ph=g_inH+(size_t)pix*64; __half* pl=g_inL+(size_t)pix*64;
    #pragma unroll
    for(int c=0;c<64;c++){
        float v=(c<10)?in[(size_t)c*HWSZ+pix]:0.f;
        __half h=__float2half_rn(v); ph[c]=h; pl[c]=__float2half_rn(v-__half2float(h));
    }
    const uint4 z=make_uint4(0,0,0,0);
    #pragma unroll
    for(int b=0;b<2;b++){
        uint4* qh=(uint4*)(g_actH[b]+(size_t)pix*128+104);
        uint4* ql=(uint4*)(g_actL[b]+(size_t)pix*128+104);
        qh[0]=z; qh[1]=z; qh[2]=z; ql[0]=z; ql[1]=z; ql[2]=z;
    }
}

// ---------------------------------------------------------------------------
// Warp-MMA implicit-GEMM conv (R10 configuration, fp16 split).
// ---------------------------------------------------------------------------
#define SMEM_MM (1024 + 2*23040 + 2*26624)

template<int CBIN,bool LEAKY>
__global__ __launch_bounds__(256,2)
void convMMA(const __half* __restrict__ aH,const __half* __restrict__ aL,
             const __half* __restrict__ wH,const __half* __restrict__ wL,
             const float* __restrict__ bias,
             __half* __restrict__ oH,__half* __restrict__ oL)
{
    extern __shared__ char dyn[];
    __shared__ float s_bias[104];
    const int tid=threadIdx.x, lane=tid&31, wid=tid>>5;
    const int wm=wid>>1, wn=wid&1;
    const int x0=blockIdx.x*16, y0=blockIdx.y*8;
    char* dynp=(char*)(((uintptr_t)dyn+1023)&~(uintptr_t)1023);
    const unsigned sbase=smem_u32(dynp);
    const unsigned sA=sbase;
    const unsigned sB=sbase+2u*AHALO;
    if(tid<104) s_bias[tid]=bias[tid];

    auto stageA=[&](int cb){
        for(int idx=tid; idx<2880; idx+=256){
            const int seg=idx&7, rowq=idx>>3;
            const int row=rowq%180, hl=rowq/180;
            const int yr=row/18, col=row-yr*18;
            const int gy=y0+yr-1, gx=x0+col-1;
            const bool ok=(unsigned)gy<HH&&(unsigned)gx<WW;
            const __half* src=(hl?aL:aH)+((size_t)(ok?(gy*WW+gx):0))*(CBIN*64)+cb*64+seg*8;
            cpa16(sA+(unsigned)hl*AHALO+sw128((unsigned)(row*128+seg*16)),src,ok?16:0);
        }
    };
    auto loadB=[&](int off,int cb,int buf){
        const unsigned base=sB+(unsigned)buf*26624u;
        #pragma unroll
        for(int k=0;k<7;k++){
            const int idx=tid+k*256; if(idx>=1664) break;
            const int hl=idx>=832?1:0, rr=idx-hl*832, n=rr>>3, i=rr&7;
            const __half* src=(hl?wL:wH)+((size_t)(off*CBIN+cb)*104+n)*64+i*8;
            cpa16(base+hl*13312u+sw128((unsigned)(n*128+i*16)),src,16);
        }
    };

    float C[7][2][4];
    #pragma unroll
    for(int t=0;t<7;t++)
        #pragma unroll
        for(int mt=0;mt<2;mt++)
            #pragma unroll
            for(int q=0;q<4;q++) C[t][mt][q]=0.f;

    const int brow0=(wm*2+0+1)*18+(lane&15)+1;
    const int brow1=(wm*2+1+1)*18+(lane&15)+1;
    const unsigned klane=((lane&16)?16u:0u);
    const int nbase=wn*48;

    for(int cb=0;cb<CBIN;cb++){
        if(cb>0) __syncthreads();            // protect A halo reuse
        stageA(cb);
        loadB(0,cb,0);
        cpa_commit();
        for(int s=0;s<9;s++){
            cpa_wait0();
            __syncthreads();
            if(s<8){ loadB(s+1,cb,(s+1)&1); cpa_commit(); }
            const int rdel=(s/3-1)*18+(s%3-1);
            const unsigned bB=sB+(unsigned)(s&1)*26624u;
            if(CBIN==1)    computeStage<1,7>(sA,bB,13312u,rdel,brow0,brow1,klane,nbase,lane,C);
            else if(cb==0) computeStage<4,7>(sA,bB,13312u,rdel,brow0,brow1,klane,nbase,lane,C);
            else           computeStage<3,7>(sA,bB,13312u,rdel,brow0,brow1,klane,nbase,lane,C);
        }
    }
    __syncthreads();

    // ---- epilogue: stage in smem, coalesced uint4 stores ----
    char* s_hi=dynp;
    char* s_lo=dynp+26624;
    #pragma unroll
    for(int t=0;t<7;t++){
        if(wn==1 && t==0) continue;          // n48-55 duplicate: keep wn0 copy
        const int n0=wn*48+t*8+2*(lane&3);
        #pragma unroll
        for(int mt=0;mt<2;mt++){
            const int mr=wm*32+mt*16+(lane>>2);
            #pragma unroll
            for(int h=0;h<2;h++){
                const int m=mr+h*8;
                float v0=C[t][mt][2*h+0]+s_bias[n0];
                float v1=C[t][mt][2*h+1]+s_bias[n0+1];
                if(LEAKY){ v0=(v0>0.f)?v0:0.01f*v0; v1=(v1>0.f)?v1:0.01f*v1; }
                __half h0,h1;
                const uint32_t hp=pack_h(v0,v1,h0,h1);
                const uint32_t lp=pack_h(v0-__half2float(h0),v1-__half2float(h1),h0,h1);
                *(uint32_t*)(s_hi + m*208 + n0*2)=hp;
                *(uint32_t*)(s_lo + m*208 + n0*2)=lp;
            }
        }
    }
    __syncthreads();
    for(int idx=tid; idx<3328; idx+=256){
        const int buf=idx>=1664; const int r=idx-buf*1664;
        const int px=r/13, q=r-px*13;
        const uint4 val=*(uint4*)((buf?s_lo:s_hi) + px*208 + q*16);
        const int pix=(y0+(px>>4))*WW+x0+(px&15);
        *(uint4*)((buf?oL:oH)+(size_t)pix*128+q*8)=val;
    }
}

// ---------------------------------------------------------------------------
// conv_last as MMA + FUSED kernel regression partials (fp16 split).
// ---------------------------------------------------------------------------
#define SMEM_CL (1024 + 2*23040 + 2*28672)
__global__ __launch_bounds__(256,2)
void convlastMMA(const __half* __restrict__ aH,const __half* __restrict__ aL,
                 const float* __restrict__ rgb)
{
    extern __shared__ char dyn[];
    __shared__ float s_bias[112];
    const int tid=threadIdx.x, lane=tid&31, wid=tid>>5;
    const int wm=wid>>1, wn=wid&1;
    const int x0=blockIdx.x*16, y0=blockIdx.y*8, z=blockIdx.z;
    char* dynp=(char*)(((uintptr_t)dyn+1023)&~(uintptr_t)1023);
    const unsigned sbase=smem_u32(dynp);
    const unsigned sA=sbase;
    const unsigned sB=sbase+2u*AHALO;
    if(tid<112) s_bias[tid]=g_biasL[z*112+tid];

    auto stageA=[&](int cb){
        for(int idx=tid; idx<2880; idx+=256){
            const int seg=idx&7, rowq=idx>>3;
            const int row=rowq%180, hl=rowq/180;
            const int yr=row/18, col=row-yr*18;
            const int gy=y0+yr-1, gx=x0+col-1;
            const bool ok=(unsigned)gy<HH&&(unsigned)gx<WW;
            const __half* src=(hl?aL:aH)+((size_t)(ok?(gy*WW+gx):0))*128+cb*64+seg*8;
            cpa16(sA+(unsigned)hl*AHALO+sw128((unsigned)(row*128+seg*16)),src,ok?16:0);
        }
    };
    auto loadB=[&](int off,int cb,int buf){
        const unsigned base=sB+(unsigned)buf*28672u;
        #pragma unroll
        for(int k=0;k<7;k++){
            const int idx=tid+k*256;
            const int hl=idx>=896?1:0, rr=idx-hl*896, n=rr>>3, i=rr&7;
            const __half* src=(hl?g_wlL:g_wlH)+((size_t)(off*2+cb)*448+z*112+n)*64+i*8;
            cpa16(base+hl*14336u+sw128((unsigned)(n*128+i*16)),src,16);
        }
    };

    float C[7][2][4];
    #pragma unroll
    for(int t=0;t<7;t++)
        #pragma unroll
        for(int mt=0;mt<2;mt++)
            #pragma unroll
            for(int q=0;q<4;q++) C[t][mt][q]=0.f;

    const int brow0=(wm*2+0+1)*18+(lane&15)+1;
    const int brow1=(wm*2+1+1)*18+(lane&15)+1;
    const unsigned klane=((lane&16)?16u:0u);
    const int nbase=wn*56;

    for(int cb=0;cb<2;cb++){
        if(cb>0) __syncthreads();
        stageA(cb);
        loadB(0,cb,0);
        cpa_commit();
        for(int s=0;s<9;s++){
            cpa_wait0();
            __syncthreads();
            if(s<8){ loadB(s+1,cb,(s+1)&1); cpa_commit(); }
            const int rdel=(s/3-1)*18+(s%3-1);
            const unsigned bB=sB+(unsigned)(s&1)*28672u;
            if(cb==0) computeStage<4,7>(sA,bB,14336u,rdel,brow0,brow1,klane,nbase,lane,C);
            else      computeStage<3,7>(sA,bB,14336u,rdel,brow0,brow1,klane,nbase,lane,C);
        }
    }
    __syncthreads();

    // ---- epilogue 1: W tile into smem [112 oc][128 px] fp32 ----
    float* s_W=(float*)dynp;
    #pragma unroll
    for(int t=0;t<7;t++){
        const int n0=wn*56+t*8+2*(lane&3);
        #pragma unroll
        for(int mt=0;mt<2;mt++){
            const int mr=wm*32+mt*16+(lane>>2);
            #pragma unroll
            for(int h=0;h<2;h++){
                const int m=mr+h*8;
                s_W[n0*128+m]    =C[t][mt][2*h+0]+s_bias[n0];
                s_W[(n0+1)*128+m]=C[t][mt][2*h+1]+s_bias[n0+1];
            }
        }
    }
    // ---- epilogue 2: stage rgb halo (13 rows x 36 cols x 3 ch) ----
    float* s_rgb=(float*)(dynp+57344);
    const int d0=(z*112)/21;
    for(int idx=tid; idx<3*13*36; idx+=256){
        const int cl=idx%36, t1=idx/36, rr=t1%13, cc=t1/13;
        const int gy=y0+rr+d0-10, gx=x0+cl-10;
        s_rgb[(cc*13+rr)*36+cl]=((unsigned)gy<HH&&(unsigned)gx<WW)?rgb[(size_t)cc*HWSZ+gy*WW+gx]:0.f;
    }
    __syncthreads();

    // ---- epilogue 3: per-pixel partial regression over this z's 112 k's ----
    if(tid<128){
        const int py=tid>>4, pxx=tid&15;
        float sr=0.f,sg=0.f,sb=0.f,ss=0.f;
        for(int j=0;j<112;j++){
            const int k=z*112+j;
            const int dyk=k/21, dxk=k-dyk*21;
            const float wv=s_W[j*128+tid];
            const float* rg=s_rgb+((py+dyk-d0)*36+pxx+dxk);
            sr=fmaf(wv,rg[0],sr);
            sg=fmaf(wv,rg[13*36],sg);
            sb=fmaf(wv,rg[2*13*36],sb);
            ss+=wv;
        }
        const int pix=(y0+py)*WW+x0+pxx;
        g_part[(size_t)(z*4+0)*HWSZ+pix]=sr;
        g_part[(size_t)(z*4+1)*HWSZ+pix]=sg;
        g_part[(size_t)(z*4+2)*HWSZ+pix]=sb;
        g_part[(size_t)(z*4+3)*HWSZ+pix]=ss;
    }
}

// ---------------------------------------------------------------------------
__global__ __launch_bounds__(256)
void finalize_k(float* __restrict__ out){
    const int i=blockIdx.x*blockDim.x+threadIdx.x; if(i>=HWSZ) return;
    float sr=0.f,sg=0.f,sb=0.f,ss=0.f;
    #pragma unroll
    for(int zz=0;zz<4;zz++){
        const float* p=g_part+(size_t)(zz*4)*HWSZ+i;
        sr+=p[0]; sg+=p[(size_t)HWSZ]; sb+=p[(size_t)2*HWSZ]; ss+=p[(size_t)3*HWSZ];
    }
    const float inv=1.f/(ss+1e-6f);
    out[i]=sr*inv; out[(size_t)HWSZ+i]=sg*inv; out[(size_t)2*HWSZ+i]=sb*inv;
}

// ---------------------------------------------------------------------------
extern "C" void kernel_launch(void* const* d_in,const int* in_sizes,int n_in,void* d_out,int out_size)
{
    const float* input=(const float*)d_in[0];
    const float* w0=(const float*)d_in[2];
    const float* b0=(const float*)d_in[3];
    const float* w_mid=(const float*)d_in[4];
    const float* b_mid=(const float*)d_in[5];
    const float* w_last=(const float*)d_in[6];
    const float* b_last=(const float*)d_in[7];
    float* out=(float*)d_out;

    cudaFuncSetAttribute(convMMA<1,false>,cudaFuncAttributeMaxDynamicSharedMemorySize,SMEM_MM);
    cudaFuncSetAttribute(convMMA<2,true>,cudaFuncAttributeMaxDynamicSharedMemorySize,SMEM_MM);
    cudaFuncSetAttribute(convlastMMA,cudaFuncAttributeMaxDynamicSharedMemorySize,SMEM_CL);

    __half *aH,*aL,*iH,*iL,*wmH,*wmL,*w0H,*w0L; float *bias;
    cudaGetSymbolAddress((void**)&aH,g_actH); cudaGetSymbolAddress((void**)&aL,g_actL);
    cudaGetSymbolAddress((void**)&iH,g_inH);  cudaGetSymbolAddress((void**)&iL,g_inL);
    cudaGetSymbolAddress((void**)&wmH,g_wmH); cudaGetSymbolAddress((void**)&wmL,g_wmL);
    cudaGetSymbolAddress((void**)&w0H,g_w0H); cudaGetSymbolAddress((void**)&w0L,g_w0L);
    cudaGetSymbolAddress((void**)&bias,g_bias);
    const size_t ACT=(size_t)HWSZ*128;
    const size_t WL=(size_t)9*2*104*64;

    const int NPREP=NW0+NWM+NWL+NBM+NBL;
    prepW_k<<<(NPREP+255)/256,256>>>(w0,w_mid,w_last,b0,b_mid,b_last);
    prepI_k<<<HWSZ/256,256>>>(input);

    const dim3 gmm(WW/16,HH/8);
    convMMA<1,false><<<gmm,256,SMEM_MM>>>(iH,iL,w0H,w0L,bias,aH,aL);
    for(int l=0;l<23;l++){
        const int rd=l&1, wr=1-rd;
        convMMA<2,true><<<gmm,256,SMEM_MM>>>(aH+rd*ACT,aL+rd*ACT,wmH+(size_t)l*WL,wmL+(size_t)l*WL,
            bias+(l+1)*104,aH+wr*ACT,aL+wr*ACT);
    }
    convlastMMA<<<dim3(WW/16,HH/8,4),256,SMEM_CL>>>(aH+ACT,aL+ACT,input);

    finalize_k<<<(HWSZ+255)/256,256>>>(out);
}

// round 17
// speedup vs baseline: 1.4436x; 1.4436x over previous
#include <cuda_runtime.h>
#include <cuda_fp16.h>
#include <cstdint>

#define HH 512
#define WW 1024
#define HWSZ (HH*WW)

// ---------------- device scratch ----------------
__device__ __half g_act[2][(size_t)HWSZ*128];   // activations, single fp16, NHWC C=128
__device__ __half g_in[(size_t)HWSZ*64];        // layer0 input, fp16, NHWC C=64
__device__ float g_part[(size_t)16*HWSZ];       // per-z partials: [z*4+{r,g,b,sum}][HW]
__device__ __half g_wmH[(size_t)23*9*2*104*64];
__device__ __half g_wmL[(size_t)23*9*2*104*64];
__device__ __half g_w0H[(size_t)9*104*64];
__device__ __half g_w0L[(size_t)9*104*64];
__device__ __half g_wlH[(size_t)9*2*448*64];
__device__ __half g_wlL[(size_t)9*2*448*64];
__device__ float g_bias[24*104];
__device__ float g_biasL[448];

// ---------------- helpers ----------------
__device__ __forceinline__ unsigned smem_u32(const void* p){unsigned a;asm("{ .reg .u64 t; cvta.to.shared.u64 t, %1; cvt.u32.u64 %0, t; }":"=r"(a):"l"(p));return a;}
__device__ __forceinline__ void cpa16(unsigned d,const void* s,int sz){asm volatile("cp.async.cg.shared.global [%0], [%1], 16, %2;"::"r"(d),"l"(s),"r"(sz));}
__device__ __forceinline__ void cpa_commit(){asm volatile("cp.async.commit_group;");}
__device__ __forceinline__ void cpa_wait0(){asm volatile("cp.async.wait_group 0;");}
__device__ __forceinline__ unsigned sw128(unsigned o){return o^((o>>3)&0x70);}
__device__ __forceinline__ void ldsm4(uint32_t* r, unsigned a){
    asm volatile("ldmatrix.sync.aligned.m8n8.x4.shared.b16 {%0,%1,%2,%3}, [%4];"
        :"=r"(r[0]),"=r"(r[1]),"=r"(r[2]),"=r"(r[3]):"r"(a));
}
__device__ __forceinline__ void ldsm2(uint32_t* r, unsigned a){
    asm volatile("ldmatrix.sync.aligned.m8n8.x2.shared.b16 {%0,%1}, [%2];"
        :"=r"(r[0]),"=r"(r[1]):"r"(a));
}
__device__ __forceinline__ void mma16816(float* c, const uint32_t* a, const uint32_t* b){
    asm volatile("mma.sync.aligned.m16n8k16.row.col.f32.f16.f16.f32 "
        "{%0,%1,%2,%3}, {%4,%5,%6,%7}, {%8,%9}, {%0,%1,%2,%3};"
        :"+f"(c[0]),"+f"(c[1]),"+f"(c[2]),"+f"(c[3])
        :"r"(a[0]),"r"(a[1]),"r"(a[2]),"r"(a[3]),"r"(b[0]),"r"(b[1]));
}

#define AHALO 23040u

// 2-pass compute for one (offset, ch-block) stage: A (fp16) x (B_hi, B_lo).
template<int KCMAX,int NT>
__device__ __forceinline__ void computeStage(
    unsigned sA, unsigned bB, unsigned bLoff, int rdel,
    int brow0, int brow1, unsigned klane, int nbase, int lane,
    float C[7][2][4])
{
    const int br[2]={brow0,brow1};
    #pragma unroll
    for(int kc=0;kc<KCMAX;kc++){
        uint32_t ah[2][4], bh[7][2], bl[7][2];
        #pragma unroll
        for(int mt=0;mt<2;mt++){
            const unsigned rel=(unsigned)((br[mt]+rdel)*128)+(unsigned)(kc*32)+klane;
            ldsm4(ah[mt], sA+sw128(rel));
        }
        constexpr int NP=NT/2;
        #pragma unroll
        for(int p=0;p<NP;p++){
            const unsigned rb=(unsigned)((nbase+p*16+(lane&7)+((lane&16)?8:0))*128 + kc*32 + ((lane&8)?16:0));
            uint32_t t4[4];
            ldsm4(t4, bB+sw128(rb));
            bh[2*p][0]=t4[0]; bh[2*p][1]=t4[1]; bh[2*p+1][0]=t4[2]; bh[2*p+1][1]=t4[3];
            ldsm4(t4, bB+bLoff+sw128(rb));
            bl[2*p][0]=t4[0]; bl[2*p][1]=t4[1]; bl[2*p+1][0]=t4[2]; bl[2*p+1][1]=t4[3];
        }
        if(NT&1){
            const unsigned rb6=(unsigned)((nbase+(NP*16)+(lane&7))*128 + kc*32 + ((lane&8)?16:0));
            ldsm2(bh[NT-1], bB+sw128(rb6));
            ldsm2(bl[NT-1], bB+bLoff+sw128(rb6));
        }
        #pragma unroll
        for(int t=0;t<NT;t++)
            #pragma unroll
            for(int mt=0;mt<2;mt++) mma16816(C[t][mt], ah[mt], bh[t]);
        #pragma unroll
        for(int t=0;t<NT;t++)
            #pragma unroll
            for(int mt=0;mt<2;mt++) mma16816(C[t][mt], ah[mt], bl[t]);
    }
}

// ---------------- prep kernels ----------------
#define NW0 (9*104*64)
#define NWM (23*18*104*64)
#define NWL (9*2*448*64)
#define NBM (24*104)
#define NBL 448
__global__ void prepW_k(const float* __restrict__ w0,const float* __restrict__ wm,
                        const float* __restrict__ wl,const float* __restrict__ b0,
                        const float* __restrict__ bm,const float* __restrict__ bl){
    int idx=blockIdx.x*blockDim.x+threadIdx.x;
    if(idx<NW0){
        const int j=idx&63, n=(idx>>6)%104, off=(idx>>6)/104;
        float v=(n<100&&j<10)?w0[((size_t)n*10+j)*9+off]:0.f;
        __half h=__float2half_rn(v); g_w0H[idx]=h; g_w0L[idx]=__float2half_rn(v-__half2float(h));
        return;
    }
    idx-=NW0;
    if(idx<NWM){
        const int j=idx&63, n=(idx>>6)%104;
        const int rest=(idx>>6)/104, cb=rest%2, rest2=rest/2, off=rest2%9, l=rest2/9;
        const int ic=cb*64+j;
        float v=(n<100&&ic<100)?wm[(((size_t)l*100+n)*100+ic)*9+off]:0.f;
        __half h=__float2half_rn(v); g_wmH[idx]=h; g_wmL[idx]=__float2half_rn(v-__half2float(h));
        return;
    }
    idx-=NWM;
    if(idx<NWL){
        const int j=idx&63, n=(idx>>6)%448;
        const int rest=(idx>>6)/448, cb=rest%2, off=rest/2;
        const int ic=cb*64+j;
        float v=(n<441&&ic<100)?wl[((size_t)n*100+ic)*9+off]:0.f;
        __half h=__float2half_rn(v); g_wlH[idx]=h; g_wlL[idx]=__float2half_rn(v-__half2float(h));
        return;
    }
    idx-=NWL;
    if(idx<NBM){
        const int n=idx%104,l=idx/104; g_bias[idx]=(n<100)?(l==0?b0[n]:bm[(l-1)*100+n]):0.f;
        return;
    }
    idx-=NBM;
    if(idx<NBL) g_biasL[idx]=(idx<441)?bl[idx]:0.f;
}
__global__ void prepI_k(const float* __restrict__ in){
    const int pix=blockIdx.x*blockDim.x+threadIdx.x; if(pix>=HWSZ) return;
    __half* ph=g_in+(size_t)pix*64;
    #pragma unroll
    for(int c=0;c<64;c++){
        float v=(c<10)?in[(size_t)c*HWSZ+pix]:0.f;
        ph[c]=__float2half_rn(v);
    }
    const uint4 z=make_uint4(0,0,0,0);
    #pragma unroll
    for(int b=0;b<2;b++){
        uint4* qh=(uint4*)(g_act[b]+(size_t)pix*128+104);
        qh[0]=z; qh[1]=z; qh[2]=z;
    }
}

// ---------------------------------------------------------------------------
// Warp-MMA implicit-GEMM conv: single-fp16 activations, split weights, 2-pass.
// smem: A halo 23040 | B 2x26624. 2 CTAs/SM.
// ---------------------------------------------------------------------------
#define SMEM_MM (1024 + 23040 + 2*26624)

template<int CBIN,bool LEAKY>
__global__ __launch_bounds__(256,2)
void convMMA(const __half* __restrict__ aA,
             const __half* __restrict__ wH,const __half* __restrict__ wL,
             const float* __restrict__ bias,
             __half* __restrict__ oA)
{
    extern __shared__ char dyn[];
    __shared__ float s_bias[104];
    const int tid=threadIdx.x, lane=tid&31, wid=tid>>5;
    const int wm=wid>>1, wn=wid&1;
    const int x0=blockIdx.x*16, y0=blockIdx.y*8;
    char* dynp=(char*)(((uintptr_t)dyn+1023)&~(uintptr_t)1023);
    const unsigned sbase=smem_u32(dynp);
    const unsigned sA=sbase;
    const unsigned sB=sbase+AHALO;
    if(tid<104) s_bias[tid]=bias[tid];

    auto stageA=[&](int cb){
        for(int idx=tid; idx<1440; idx+=256){
            const int seg=idx&7, row=idx>>3;     // 180 rows
            const int yr=row/18, col=row-yr*18;
            const int gy=y0+yr-1, gx=x0+col-1;
            const bool ok=(unsigned)gy<HH&&(unsigned)gx<WW;
            const __half* src=aA+((size_t)(ok?(gy*WW+gx):0))*(CBIN*64)+cb*64+seg*8;
            cpa16(sA+sw128((unsigned)(row*128+seg*16)),src,ok?16:0);
        }
    };
    auto loadB=[&](int off,int cb,int buf){
        const unsigned base=sB+(unsigned)buf*26624u;
        #pragma unroll
        for(int k=0;k<7;k++){
            const int idx=tid+k*256; if(idx>=1664) break;
            const int hl=idx>=832?1:0, rr=idx-hl*832, n=rr>>3, i=rr&7;
            const __half* src=(hl?wL:wH)+((size_t)(off*CBIN+cb)*104+n)*64+i*8;
            cpa16(base+hl*13312u+sw128((unsigned)(n*128+i*16)),src,16);
        }
    };

    float C[7][2][4];
    #pragma unroll
    for(int t=0;t<7;t++)
        #pragma unroll
        for(int mt=0;mt<2;mt++)
            #pragma unroll
            for(int q=0;q<4;q++) C[t][mt][q]=0.f;

    const int brow0=(wm*2+0+1)*18+(lane&15)+1;
    const int brow1=(wm*2+1+1)*18+(lane&15)+1;
    const unsigned klane=((lane&16)?16u:0u);
    const int nbase=wn*48;

    for(int cb=0;cb<CBIN;cb++){
        if(cb>0) __syncthreads();            // protect A halo reuse
        stageA(cb);
        loadB(0,cb,0);
        cpa_commit();
        for(int s=0;s<9;s++){
            cpa_wait0();
            __syncthreads();
            if(s<8){ loadB(s+1,cb,(s+1)&1); cpa_commit(); }
            const int rdel=(s/3-1)*18+(s%3-1);
            const unsigned bB=sB+(unsigned)(s&1)*26624u;
            if(CBIN==1)    computeStage<1,7>(sA,bB,13312u,rdel,brow0,brow1,klane,nbase,lane,C);
            else if(cb==0) computeStage<4,7>(sA,bB,13312u,rdel,brow0,brow1,klane,nbase,lane,C);
            else           computeStage<3,7>(sA,bB,13312u,rdel,brow0,brow1,klane,nbase,lane,C);
        }
    }
    __syncthreads();

    // ---- epilogue: stage in smem [128px][104ch] fp16, coalesced uint4 stores ----
    char* s_o=dynp;                          // 128*208 = 26624 bytes
    #pragma unroll
    for(int t=0;t<7;t++){
        if(wn==1 && t==0) continue;          // n48-55 duplicate: keep wn0 copy
        const int n0=wn*48+t*8+2*(lane&3);
        #pragma unroll
        for(int mt=0;mt<2;mt++){
            const int mr=wm*32+mt*16+(lane>>2);
            #pragma unroll
            for(int h=0;h<2;h++){
                const int m=mr+h*8;
                float v0=C[t][mt][2*h+0]+s_bias[n0];
                float v1=C[t][mt][2*h+1]+s_bias[n0+1];
                if(LEAKY){ v0=(v0>0.f)?v0:0.01f*v0; v1=(v1>0.f)?v1:0.01f*v1; }
                const __half h0=__float2half_rn(v0), h1=__float2half_rn(v1);
                *(uint32_t*)(s_o + m*208 + n0*2)=
                    (unsigned)__half_as_ushort(h0)|((unsigned)__half_as_ushort(h1)<<16);
            }
        }
    }
    __syncthreads();
    for(int idx=tid; idx<1664; idx+=256){
        const int px=idx/13, q=idx-px*13;
        const uint4 val=*(uint4*)(s_o + px*208 + q*16);
        const int pix=(y0+(px>>4))*WW+x0+(px&15);
        *(uint4*)(oA+(size_t)pix*128+q*8)=val;
    }
}

// ---------------------------------------------------------------------------
// conv_last as MMA + FUSED kernel regression partials (2-pass split).
// ---------------------------------------------------------------------------
#define SMEM_CL (1024 + 23040 + 2*28672)
__global__ __launch_bounds__(256,2)
void convlastMMA(const __half* __restrict__ aA, const float* __restrict__ rgb)
{
    extern __shared__ char dyn[];
    __shared__ float s_bias[112];
    const int tid=threadIdx.x, lane=tid&31, wid=tid>>5;
    const int wm=wid>>1, wn=wid&1;
    const int x0=blockIdx.x*16, y0=blockIdx.y*8, z=blockIdx.z;
    char* dynp=(char*)(((uintptr_t)dyn+1023)&~(uintptr_t)1023);
    const unsigned sbase=smem_u32(dynp);
    const unsigned sA=sbase;
    const unsigned sB=sbase+AHALO;
    if(tid<112) s_bias[tid]=g_biasL[z*112+tid];

    auto stageA=[&](int cb){
        for(int idx=tid; idx<1440; idx+=256){
            const int seg=idx&7, row=idx>>3;
            const int yr=row/18, col=row-yr*18;
            const int gy=y0+yr-1, gx=x0+col-1;
            const bool ok=(unsigned)gy<HH&&(unsigned)gx<WW;
            const __half* src=aA+((size_t)(ok?(gy*WW+gx):0))*128+cb*64+seg*8;
            cpa16(sA+sw128((unsigned)(row*128+seg*16)),src,ok?16:0);
        }
    };
    auto loadB=[&](int off,int cb,int buf){
        const unsigned base=sB+(unsigned)buf*28672u;
        #pragma unroll
        for(int k=0;k<7;k++){
            const int idx=tid+k*256;
            const int hl=idx>=896?1:0, rr=idx-hl*896, n=rr>>3, i=rr&7;
            const __half* src=(hl?g_wlL:g_wlH)+((size_t)(off*2+cb)*448+z*112+n)*64+i*8;
            cpa16(base+hl*14336u+sw128((unsigned)(n*128+i*16)),src,16);
        }
    };

    float C[7][2][4];
    #pragma unroll
    for(int t=0;t<7;t++)
        #pragma unroll
        for(int mt=0;mt<2;mt++)
            #pragma unroll
            for(int q=0;q<4;q++) C[t][mt][q]=0.f;

    const int brow0=(wm*2+0+1)*18+(lane&15)+1;
    const int brow1=(wm*2+1+1)*18+(lane&15)+1;
    const unsigned klane=((lane&16)?16u:0u);
    const int nbase=wn*56;

    for(int cb=0;cb<2;cb++){
        if(cb>0) __syncthreads();
        stageA(cb);
        loadB(0,cb,0);
        cpa_commit();
        for(int s=0;s<9;s++){
            cpa_wait0();
            __syncthreads();
            if(s<8){ loadB(s+1,cb,(s+1)&1); cpa_commit(); }
            const int rdel=(s/3-1)*18+(s%3-1);
            const unsigned bB=sB+(unsigned)(s&1)*28672u;
            if(cb==0) computeStage<4,7>(sA,bB,14336u,rdel,brow0,brow1,klane,nbase,lane,C);
            else      computeStage<3,7>(sA,bB,14336u,rdel,brow0,brow1,klane,nbase,lane,C);
        }
    }
    __syncthreads();

    // ---- epilogue 1: W tile into smem [112 oc][128 px] fp32 ----
    float* s_W=(float*)dynp;
    #pragma unroll
    for(int t=0;t<7;t++){
        const int n0=wn*56+t*8+2*(lane&3);
        #pragma unroll
        for(int mt=0;mt<2;mt++){
            const int mr=wm*32+mt*16+(lane>>2);
            #pragma unroll
            for(int h=0;h<2;h++){
                const int m=mr+h*8;
                s_W[n0*128+m]    =C[t][mt][2*h+0]+s_bias[n0];
                s_W[(n0+1)*128+m]=C[t][mt][2*h+1]+s_bias[n0+1];
            }
        }
    }
    // ---- epilogue 2: stage rgb halo (13 rows x 36 cols x 3 ch) ----
    float* s_rgb=(float*)(dynp+57344);
    const int d0=(z*112)/21;
    for(int idx=tid; idx<3*13*36; idx+=256){
        const int cl=idx%36, t1=idx/36, rr=t1%13, cc=t1/13;
        const int gy=y0+rr+d0-10, gx=x0+cl-10;
        s_rgb[(cc*13+rr)*36+cl]=((unsigned)gy<HH&&(unsigned)gx<WW)?rgb[(size_t)cc*HWSZ+gy*WW+gx]:0.f;
    }
    __syncthreads();

    // ---- epilogue 3: per-pixel partial regression over this z's 112 k's ----
    if(tid<128){
        const int py=tid>>4, pxx=tid&15;
        float sr=0.f,sg=0.f,sb=0.f,ss=0.f;
        for(int j=0;j<112;j++){
            const int k=z*112+j;
            const int dyk=k/21, dxk=k-dyk*21;
            const float wv=s_W[j*128+tid];
            const float* rg=s_rgb+((py+dyk-d0)*36+pxx+dxk);
            sr=fmaf(wv,rg[0],sr);
            sg=fmaf(wv,rg[13*36],sg);
            sb=fmaf(wv,rg[2*13*36],sb);
            ss+=wv;
        }
        const int pix=(y0+py)*WW+x0+pxx;
        g_part[(size_t)(z*4+0)*HWSZ+pix]=sr;
        g_part[(size_t)(z*4+1)*HWSZ+pix]=sg;
        g_part[(size_t)(z*4+2)*HWSZ+pix]=sb;
        g_part[(size_t)(z*4+3)*HWSZ+pix]=ss;
    }
}

// ---------------------------------------------------------------------------
__global__ __launch_bounds__(256)
void finalize_k(float* __restrict__ out){
    const int i=blockIdx.x*blockDim.x+threadIdx.x; if(i>=HWSZ) return;
    float sr=0.f,sg=0.f,sb=0.f,ss=0.f;
    #pragma unroll
    for(int zz=0;zz<4;zz++){
        const float* p=g_part+(size_t)(zz*4)*HWSZ+i;
        sr+=p[0]; sg+=p[(size_t)HWSZ]; sb+=p[(size_t)2*HWSZ]; ss+=p[(size_t)3*HWSZ];
    }
    const float inv=1.f/(ss+1e-6f);
    out[i]=sr*inv; out[(size_t)HWSZ+i]=sg*inv; out[(size_t)2*HWSZ+i]=sb*inv;
}

// ---------------------------------------------------------------------------
extern "C" void kernel_launch(void* const* d_in,const int* in_sizes,int n_in,void* d_out,int out_size)
{
    const float* input=(const float*)d_in[0];
    const float* w0=(const float*)d_in[2];
    const float* b0=(const float*)d_in[3];
    const float* w_mid=(const float*)d_in[4];
    const float* b_mid=(const float*)d_in[5];
    const float* w_last=(const float*)d_in[6];
    const float* b_last=(const float*)d_in[7];
    float* out=(float*)d_out;

    cudaFuncSetAttribute(convMMA<1,false>,cudaFuncAttributeMaxDynamicSharedMemorySize,SMEM_MM);
    cudaFuncSetAttribute(convMMA<2,true>,cudaFuncAttributeMaxDynamicSharedMemorySize,SMEM_MM);
    cudaFuncSetAttribute(convlastMMA,cudaFuncAttributeMaxDynamicSharedMemorySize,SMEM_CL);

    __half *aA,*iA,*wmH,*wmL,*w0H,*w0L; float *bias;
    cudaGetSymbolAddress((void**)&aA,g_act);
    cudaGetSymbolAddress((void**)&iA,g_in);
    cudaGetSymbolAddress((void**)&wmH,g_wmH); cudaGetSymbolAddress((void**)&wmL,g_wmL);
    cudaGetSymbolAddress((void**)&w0H,g_w0H); cudaGetSymbolAddress((void**)&w0L,g_w0L);
    cudaGetSymbolAddress((void**)&bias,g_bias);
    const size_t ACT=(size_t)HWSZ*128;
    const size_t WL=(size_t)9*2*104*64;

    const int NPREP=NW0+NWM+NWL+NBM+NBL;
    prepW_k<<<(NPREP+255)/256,256>>>(w0,w_mid,w_last,b0,b_mid,b_last);
    prepI_k<<<HWSZ/256,256>>>(input);

    const dim3 gmm(WW/16,HH/8);
    convMMA<1,false><<<gmm,256,SMEM_MM>>>(iA,w0H,w0L,bias,aA);
    for(int l=0;l<23;l++){
        const int rd=l&1, wr=1-rd;
        convMMA<2,true><<<gmm,256,SMEM_MM>>>(aA+rd*ACT,wmH+(size_t)l*WL,wmL+(size_t)l*WL,
            bias+(l+1)*104,aA+wr*ACT);
    }
    // features are in buffer 1 after 23 mid layers
    convlastMMA<<<dim3(WW/16,HH/8,4),256,SMEM_CL>>>(aA+ACT,input);

    finalize_k<<<(HWSZ+255)/256,256>>>(out);
}